// round 15
// baseline (speedup 1.0000x reference)
#include <cuda_runtime.h>
#include <cuda_fp16.h>
#include <cstdint>
#include <math.h>

#define B_ 64
#define O_ 64
#define I_ 1152
#define EPSF 1e-8f

// ---- scratch ----
__device__ __half g_Vh[75497472];        // [o][i][b][e] fp16
__device__ float g_aiT[I_*B_];
__device__ float g_sumai[B_];            // zero-init; re-zeroed in k4 each call
__device__ float g_p0s1[36*B_*O_*16];
__device__ float g_p0s2[36*B_*O_*16];
__device__ float g_mean[B_*O_*16];
__device__ float g_i2v[B_*O_*16];
__device__ float g_coef[B_*O_];
__device__ float g_p1s1[B_*72*O_*16];
__device__ float g_p1s2[B_*72*O_*16];
__device__ float g_p1rs[B_*72*O_];

__device__ __forceinline__ unsigned toTf32(float f){
    unsigned r; asm("cvt.rna.tf32.f32 %0,%1;" : "=r"(r) : "f"(f)); return r;
}
__device__ __forceinline__ void mma8(float* d, const unsigned* a, const unsigned* b){
    asm volatile("mma.sync.aligned.m16n8k8.row.col.f32.tf32.tf32.f32 "
        "{%0,%1,%2,%3},{%4,%5,%6,%7},{%8,%9},{%0,%1,%2,%3};"
        : "+f"(d[0]),"+f"(d[1]),"+f"(d[2]),"+f"(d[3])
        : "r"(a[0]),"r"(a[1]),"r"(a[2]),"r"(a[3]),"r"(b[0]),"r"(b[1]));
}

// ================= K1: a_i (+ atomic per-b sum) =================
__global__ __launch_bounds__(256) void k1_ai(const float* __restrict__ u){
    int idx = blockIdx.x*256 + threadIdx.x;
    if (idx >= B_*I_) return;
    const float4* up = ((const float4*)u) + (size_t)idx*4;
    float s = 0.f;
    #pragma unroll
    for (int k=0;k<4;k++){
        float4 v = up[k];
        float x0=v.x+EPSF, x1=v.y+EPSF, x2=v.z+EPSF, x3=v.w+EPSF;
        s += x0*x0+x1*x1+x2*x2+x3*x3;
    }
    float a = sqrtf(s);
    int b = idx / I_, i = idx % I_;
    g_aiT[i*B_+b] = a;
    atomicAdd(&g_sumai[b], a);
}

// ================= K2 v6: pipelined o-tiled tf32 mma votes =================
// grid (36, 8): itile (32 i), otile (8 o). Warp w -> o = otile*8 + w.
// Double-buffered stages (2 i each), 1 barrier/stage, LDG prefetch overlapped.
__global__ __launch_bounds__(256) void k2_votes(const float* __restrict__ u,
                                               const float* __restrict__ W,
                                               const float* __restrict__ bias){
    __shared__ float sU[2][2*64*16];     // [buf][il][b][d']
    __shared__ float sW[2][8*2*16*16];   // [buf][w][il][e][d']
    __shared__ float sAi[2][2*64];
    int t = threadIdx.x;
    int w = t>>5, l = t&31, lg = l>>2, tg = l&3;
    int itile = blockIdx.x;
    int o = blockIdx.y*8 + w;

    float bs[2][2];
    #pragma unroll
    for (int et=0;et<2;et++)
      #pragma unroll
      for (int p=0;p<2;p++) bs[et][p] = bias[o*16 + et*8 + 2*tg + p] + EPSF;

    float s1[4][2][2][2], s2[4][2][2][2];
    #pragma unroll
    for (int a0=0;a0<4;a0++)
      #pragma unroll
      for (int a1=0;a1<2;a1++)
        #pragma unroll
        for (int a2=0;a2<2;a2++)
          #pragma unroll
          for (int a3=0;a3<2;a3++){ s1[a0][a1][a2][a3]=0.f; s2[a0][a1][a2][a3]=0.f; }

    const float4* Wp = (const float4*)W;
    const float4* Up = (const float4*)u;

    // staging index decompositions (fixed per thread)
    int u_b[2], u_d4[2], u_il[2];
    #pragma unroll
    for (int j=0;j<2;j++){
        int idx = t + j*256;
        u_il[j] = idx>>8; int r = idx&255; u_b[j] = r>>2; u_d4[j] = r&3;
    }
    int w_il[4], w_r[4], w_e[4], w_d4[4];
    #pragma unroll
    for (int j=0;j<4;j++){
        int f = l + j*32;
        w_il[j] = f>>6; w_r[j] = f&63; w_e[j] = w_r[j]>>2; w_d4[j] = w_r[j]&3;
    }
    int a_il = t>>6, a_b = t&63;      // valid when t<128

    float4 uReg[2], wReg[4]; float aReg = 0.f;
    // ---- prefetch stage 0 ----
    #pragma unroll
    for (int j=0;j<2;j++)
        uReg[j] = Up[((size_t)u_b[j]*I_ + itile*32 + u_il[j])*4 + u_d4[j]];
    #pragma unroll
    for (int j=0;j<4;j++)
        wReg[j] = Wp[((size_t)o*I_ + itile*32 + w_il[j])*64 + w_r[j]];
    if (t < 128) aReg = g_aiT[(itile*32 + a_il)*B_ + a_b];

    // ---- store stage 0 into buf 0 ----
    #pragma unroll
    for (int j=0;j<2;j++){
        float* dst = sU[0] + u_il[j]*1024 + u_b[j]*16 + u_d4[j];
        dst[0]=__uint_as_float(toTf32(uReg[j].x)); dst[4]=__uint_as_float(toTf32(uReg[j].y));
        dst[8]=__uint_as_float(toTf32(uReg[j].z)); dst[12]=__uint_as_float(toTf32(uReg[j].w));
    }
    #pragma unroll
    for (int j=0;j<4;j++){
        float* dst = sW[0] + ((w*2+w_il[j])*16 + w_e[j])*16 + w_d4[j];
        dst[0]=wReg[j].x; dst[4]=wReg[j].y; dst[8]=wReg[j].z; dst[12]=wReg[j].w;
    }
    if (t < 128) sAi[0][a_il*64+a_b] = aReg;
    __syncthreads();

    for (int stage=0; stage<16; stage++){
        int buf = stage & 1;
        int ibase = itile*32 + stage*2;
        // prefetch next stage
        if (stage < 15){
            int nb = ibase + 2;
            #pragma unroll
            for (int j=0;j<2;j++)
                uReg[j] = Up[((size_t)u_b[j]*I_ + nb + u_il[j])*4 + u_d4[j]];
            #pragma unroll
            for (int j=0;j<4;j++)
                wReg[j] = Wp[((size_t)o*I_ + nb + w_il[j])*64 + w_r[j]];
            if (t < 128) aReg = g_aiT[(nb + a_il)*B_ + a_b];
        }

        // compute current stage
        #pragma unroll
        for (int il=0; il<2; il++){
            int i = ibase + il;
            const float* uB = sU[buf] + il*1024;
            const float* wB = sW[buf] + ((size_t)(w*2+il))*256;

            uint4 bh[2], bl[2];
            #pragma unroll
            for (int et=0; et<2; et++){
                float4 wv = *(const float4*)(wB + (et*8+lg)*16 + 4*tg);
                unsigned hx=toTf32(wv.x), hy=toTf32(wv.y), hz=toTf32(wv.z), hw=toTf32(wv.w);
                bh[et] = make_uint4(hx, hy, hz, hw);
                bl[et] = make_uint4(toTf32(wv.x-__uint_as_float(hx)),
                                    toTf32(wv.y-__uint_as_float(hy)),
                                    toTf32(wv.z-__uint_as_float(hz)),
                                    toTf32(wv.w-__uint_as_float(hw)));
            }
            #pragma unroll
            for (int mt=0; mt<4; mt++){
                int r0 = mt*16 + lg;
                float4 ar0 = *(const float4*)(uB + r0*16 + 4*tg);
                float4 ar1 = *(const float4*)(uB + (r0+8)*16 + 4*tg);
                unsigned Ak0[4] = {__float_as_uint(ar0.x), __float_as_uint(ar1.x),
                                   __float_as_uint(ar0.y), __float_as_uint(ar1.y)};
                unsigned Ak1[4] = {__float_as_uint(ar0.z), __float_as_uint(ar1.z),
                                   __float_as_uint(ar0.w), __float_as_uint(ar1.w)};
                float ra0 = sAi[buf][il*64 + r0]*0.015625f;
                float ra1 = sAi[buf][il*64 + r0 + 8]*0.015625f;
                #pragma unroll
                for (int et=0; et<2; et++){
                    float D[4] = {0.f,0.f,0.f,0.f};
                    mma8(D, Ak0, (const unsigned*)&bh[et]);
                    mma8(D, Ak1, ((const unsigned*)&bh[et])+2);
                    mma8(D, Ak0, (const unsigned*)&bl[et]);
                    mma8(D, Ak1, ((const unsigned*)&bl[et])+2);
                    int e0 = et*8 + 2*tg;
                    float v00 = D[0]+bs[et][0], v01 = D[1]+bs[et][1];
                    float v10 = D[2]+bs[et][0], v11 = D[3]+bs[et][1];
                    __half* vp = g_Vh + (((size_t)o*I_ + i)*64 + r0)*16 + e0;
                    *(__half2*)vp         = __floats2half2_rn(v00, v01);
                    *(__half2*)(vp + 128) = __floats2half2_rn(v10, v11);
                    s1[mt][0][et][0] += ra0*v00;  s2[mt][0][et][0] += ra0*v00*v00;
                    s1[mt][0][et][1] += ra0*v01;  s2[mt][0][et][1] += ra0*v01*v01;
                    s1[mt][1][et][0] += ra1*v10;  s2[mt][1][et][0] += ra1*v10*v10;
                    s1[mt][1][et][1] += ra1*v11;  s2[mt][1][et][1] += ra1*v11*v11;
                }
            }
        }

        // store next stage into alternate buffer, single barrier
        if (stage < 15){
            int nbuf = buf ^ 1;
            #pragma unroll
            for (int j=0;j<2;j++){
                float* dst = sU[nbuf] + u_il[j]*1024 + u_b[j]*16 + u_d4[j];
                dst[0]=__uint_as_float(toTf32(uReg[j].x)); dst[4]=__uint_as_float(toTf32(uReg[j].y));
                dst[8]=__uint_as_float(toTf32(uReg[j].z)); dst[12]=__uint_as_float(toTf32(uReg[j].w));
            }
            #pragma unroll
            for (int j=0;j<4;j++){
                float* dst = sW[nbuf] + ((w*2+w_il[j])*16 + w_e[j])*16 + w_d4[j];
                dst[0]=wReg[j].x; dst[4]=wReg[j].y; dst[8]=wReg[j].z; dst[12]=wReg[j].w;
            }
            if (t < 128) sAi[nbuf][a_il*64+a_b] = aReg;
            __syncthreads();
        }
    }

    // write iter0 partials [itile][b][o][e]
    #pragma unroll
    for (int mt=0; mt<4; mt++)
      #pragma unroll
      for (int rs=0; rs<2; rs++)
        #pragma unroll
        for (int et=0; et<2; et++)
          #pragma unroll
          for (int p=0; p<2; p++){
              int b = mt*16 + lg + rs*8;
              int e = et*8 + 2*tg + p;
              size_t gidx = (((size_t)itile*B_ + b)*O_ + o)*16 + e;
              g_p0s1[gidx] = s1[mt][rs][et][p];
              g_p0s2[gidx] = s2[mt][rs][et][p];
          }
}

// ================= K3: iter0 m-step finalize =================
__global__ __launch_bounds__(256) void k3_mstep0(const float* __restrict__ beta_a,
                                                 const float* __restrict__ beta_u){
    int t = threadIdx.x;
    int lane = t & 15;
    int unit = blockIdx.x*16 + (t>>4);
    int b = unit >> 6, o = unit & 63;
    float S1=0.f, S2=0.f;
    for (int tt=0; tt<36; tt++){
        size_t base = (((size_t)tt*B_ + b)*O_ + o)*16 + lane;
        S1 += g_p0s1[base];
        S2 += g_p0s2[base];
    }
    float rs = g_sumai[b] * 0.015625f;
    float inv = 1.f/(rs + EPSF);
    float mean = S1*inv;
    float var  = (S2 - 2.f*mean*S1 + mean*mean*rs)*inv + 1e-4f;
    float lv = logf(var), pv = var;
    #pragma unroll
    for (int k=1;k<16;k<<=1){
        lv += __shfl_xor_sync(0xffffffffu, lv, k, 16);
        pv *= __shfl_xor_sync(0xffffffffu, pv, k, 16);
    }
    float cost = rs*(16.f*beta_u[o] + lv);
    float x = 0.0005f*(beta_a[o]-cost);
    float aj = 1.f/(1.f+expf(-x));
    float p1 = sqrtf(6.283185307179586f*pv + EPSF);
    size_t mb = ((size_t)b*O_+o)*16+lane;
    g_mean[mb] = mean;
    g_i2v[mb]  = 1.f/(2.f*var + EPSF);
    if (lane==0) g_coef[b*O_+o] = aj/(p1+EPSF);
}

// ================= K4: e-step + iter1 partials (V layout [o][i][b][e]) =================
__global__ __launch_bounds__(256) void k4_estep(){
    __shared__ float sMeanT[16*66];
    __shared__ float sI2vT[16*66];
    __shared__ float sCoef[64];
    __shared__ float sAi[16];
    __shared__ float sAP[16][64];
    __shared__ float sInv[16];
    int t = threadIdx.x, it = blockIdx.x, b = blockIdx.y;
    int o = t >> 2, eq = t & 3;

    // re-zero g_sumai for the next call (k3 already consumed it)
    if (it == 0 && b == 0 && t < 64) g_sumai[t] = 0.f;

    for (int idx = t; idx < 1024; idx += 256){
        int oo = idx >> 4, e = idx & 15;
        size_t g = ((size_t)b*O_ + oo)*16 + e;
        sMeanT[e*66+oo] = g_mean[g];
        sI2vT[e*66+oo]  = g_i2v[g];
    }
    if (t < 64) sCoef[t] = g_coef[b*O_+t];
    if (t < 16) sAi[t] = g_aiT[(it*16+t)*B_ + b];
    __syncthreads();

    float m0 = sMeanT[(eq*4+0)*66+o], m1 = sMeanT[(eq*4+1)*66+o];
    float m2 = sMeanT[(eq*4+2)*66+o], m3 = sMeanT[(eq*4+3)*66+o];
    float w0 = sI2vT[(eq*4+0)*66+o], w1 = sI2vT[(eq*4+1)*66+o];
    float w2 = sI2vT[(eq*4+2)*66+o], w3 = sI2vT[(eq*4+3)*66+o];
    float cf = sCoef[o];

    const __half* vbase = g_Vh + (((size_t)o*I_ + it*16)*64 + b)*16 + eq*4;
    uint2 vr[16];

    #pragma unroll
    for (int il=0; il<16; il++){
        uint2 raw = *(const uint2*)(vbase + il*1024);
        vr[il] = raw;
        float2 fa = __half22float2(*(__half2*)&raw.x);
        float2 fb = __half22float2(*(__half2*)&raw.y);
        float d0 = fa.x-m0, d1 = fa.y-m1, d2 = fb.x-m2, d3 = fb.y-m3;
        float ss = d0*d0*w0 + d1*d1*w1 + d2*d2*w2 + d3*d3*w3;
        ss += __shfl_xor_sync(0xffffffffu, ss, 1);
        ss += __shfl_xor_sync(0xffffffffu, ss, 2);
        if (eq == 0) sAP[il][o] = cf*__expf(-ss);
    }
    __syncthreads();

    {
        int i2 = t >> 4, j = t & 15;
        float v = sAP[i2][j] + sAP[i2][j+16] + sAP[i2][j+32] + sAP[i2][j+48];
        v += __shfl_xor_sync(0xffffffffu, v, 1, 16);
        v += __shfl_xor_sync(0xffffffffu, v, 2, 16);
        v += __shfl_xor_sync(0xffffffffu, v, 4, 16);
        v += __shfl_xor_sync(0xffffffffu, v, 8, 16);
        if (j == 0) sInv[i2] = 1.f/(v + EPSF);
    }
    __syncthreads();

    float s1[4]={0,0,0,0}, s2[4]={0,0,0,0}, accr=0.f;
    #pragma unroll
    for (int il=0; il<16; il++){
        float rra = sAP[il][o]*sInv[il]*sAi[il];
        float2 fa = __half22float2(*(__half2*)&vr[il].x);
        float2 fb = __half22float2(*(__half2*)&vr[il].y);
        s1[0] += rra*fa.x; s2[0] += rra*fa.x*fa.x;
        s1[1] += rra*fa.y; s2[1] += rra*fa.y*fa.y;
        s1[2] += rra*fb.x; s2[2] += rra*fb.x*fb.x;
        s1[3] += rra*fb.y; s2[3] += rra*fb.y*fb.y;
        if (eq == 0) accr += rra;
    }
    size_t base = (((size_t)b*72 + it)*O_ + o)*16 + eq*4;
    float4 a1; a1.x=s1[0]; a1.y=s1[1]; a1.z=s1[2]; a1.w=s1[3];
    float4 a2; a2.x=s2[0]; a2.y=s2[1]; a2.z=s2[2]; a2.w=s2[3];
    *(float4*)(g_p1s1+base) = a1;
    *(float4*)(g_p1s2+base) = a2;
    if (eq == 0) g_p1rs[((size_t)b*72 + it)*O_ + o] = accr;
}

// ================= K5: iter1 finalize + output =================
__global__ __launch_bounds__(256) void k5_out(const float* __restrict__ beta_a,
                                              const float* __restrict__ beta_u,
                                              float* __restrict__ out){
    int t = threadIdx.x;
    int lane = t & 15;
    int unit = blockIdx.x*16 + (t>>4);
    int b = unit >> 6, o = unit & 63;
    float S1=0.f, S2=0.f, rs=0.f;
    for (int tt=0; tt<72; tt++){
        size_t base = (((size_t)b*72 + tt)*O_ + o)*16 + lane;
        S1 += g_p1s1[base];
        S2 += g_p1s2[base];
        rs += g_p1rs[((size_t)b*72 + tt)*O_ + o];
    }
    float inv = 1.f/(rs + EPSF);
    float mean = S1*inv;
    float var  = (S2 - 2.f*mean*S1 + mean*mean*rs)*inv + 1e-4f;
    float lv = logf(var);
    float me = mean + EPSF;
    float nn = me*me;
    #pragma unroll
    for (int k=1;k<16;k<<=1){
        lv += __shfl_xor_sync(0xffffffffu, lv, k, 16);
        nn += __shfl_xor_sync(0xffffffffu, nn, k, 16);
    }
    float cost = rs*(16.f*beta_u[o] + lv);
    float x = 0.000975f*(beta_a[o]-cost);
    float aj = 1.f/(1.f+expf(-x));
    float nrm = sqrtf(nn);
    out[((size_t)b*O_+o)*16+lane] = aj*mean/(nrm + EPSF);
}

extern "C" void kernel_launch(void* const* d_in, const int* in_sizes, int n_in,
                              void* d_out, int out_size) {
    const float* u      = (const float*)d_in[0];
    const float* W      = (const float*)d_in[1];
    const float* beta_a = (const float*)d_in[2];
    const float* beta_u = (const float*)d_in[3];
    const float* bias   = (const float*)d_in[4];
    float* out = (float*)d_out;

    k1_ai<<<(B_*I_+255)/256, 256>>>(u);          // launch 1
    k2_votes<<<dim3(36, 8), 256>>>(u, W, bias);  // launch 2
    k3_mstep0<<<256, 256>>>(beta_a, beta_u);     // launch 3
    k4_estep<<<dim3(72, 64), 256>>>();           // launch 4 -> ncu slot
    k5_out<<<256, 256>>>(beta_a, beta_u, out);   // launch 5
}

// round 16
// speedup vs baseline: 1.0638x; 1.0638x over previous
#include <cuda_runtime.h>
#include <cuda_fp16.h>
#include <cstdint>
#include <math.h>

#define B_ 64
#define O_ 64
#define I_ 1152
#define EPSF 1e-8f

// ---- scratch ----
__device__ __half g_Vh[75497472];        // [o][i][b][e] fp16
__device__ float g_aiT[I_*B_];
__device__ float g_sumai[B_];            // zero-init; re-zeroed in k4 each call
__device__ float g_p0s1[36*B_*O_*16];
__device__ float g_p0s2[36*B_*O_*16];
__device__ float g_mean[B_*O_*16];
__device__ float g_i2v[B_*O_*16];
__device__ float g_coef[B_*O_];
__device__ float g_p1s1[B_*72*O_*16];
__device__ float g_p1s2[B_*72*O_*16];
__device__ float g_p1rs[B_*72*O_];

__device__ __forceinline__ unsigned toTf32(float f){
    unsigned r; asm("cvt.rna.tf32.f32 %0,%1;" : "=r"(r) : "f"(f)); return r;
}
__device__ __forceinline__ void mma8(float* d, const unsigned* a, const unsigned* b){
    asm volatile("mma.sync.aligned.m16n8k8.row.col.f32.tf32.tf32.f32 "
        "{%0,%1,%2,%3},{%4,%5,%6,%7},{%8,%9},{%0,%1,%2,%3};"
        : "+f"(d[0]),"+f"(d[1]),"+f"(d[2]),"+f"(d[3])
        : "r"(a[0]),"r"(a[1]),"r"(a[2]),"r"(a[3]),"r"(b[0]),"r"(b[1]));
}

// ================= K1: a_i (+ atomic per-b sum) =================
__global__ __launch_bounds__(256) void k1_ai(const float* __restrict__ u){
    int idx = blockIdx.x*256 + threadIdx.x;
    if (idx >= B_*I_) return;
    const float4* up = ((const float4*)u) + (size_t)idx*4;
    float s = 0.f;
    #pragma unroll
    for (int k=0;k<4;k++){
        float4 v = up[k];
        float x0=v.x+EPSF, x1=v.y+EPSF, x2=v.z+EPSF, x3=v.w+EPSF;
        s += x0*x0+x1*x1+x2*x2+x3*x3;
    }
    float a = sqrtf(s);
    int b = idx / I_, i = idx % I_;
    g_aiT[i*B_+b] = a;
    atomicAdd(&g_sumai[b], a);
}

// ================= K2 (R14 version): o-tiled tf32 mma votes =================
// grid (36, 8): itile (32 i), otile (8 o). 8 warps, warp w -> o = otile*8 + w.
__global__ __launch_bounds__(256) void k2_votes(const float* __restrict__ u,
                                               const float* __restrict__ W,
                                               const float* __restrict__ bias){
    __shared__ float sU[2*64*16];      // [il][b][d'] tf32 bits
    __shared__ float sW[8*2*16*16];    // [w][il][e][d'] raw fp32
    __shared__ float sAi[2*64];
    int t = threadIdx.x;
    int w = t>>5, l = t&31, lg = l>>2, tg = l&3;
    int itile = blockIdx.x;
    int o = blockIdx.y*8 + w;

    float bs[2][2];
    #pragma unroll
    for (int et=0;et<2;et++)
      #pragma unroll
      for (int p=0;p<2;p++) bs[et][p] = bias[o*16 + et*8 + 2*tg + p] + EPSF;

    float s1[4][2][2][2], s2[4][2][2][2];   // [mt][rowsel][et][p]
    #pragma unroll
    for (int a0=0;a0<4;a0++)
      #pragma unroll
      for (int a1=0;a1<2;a1++)
        #pragma unroll
        for (int a2=0;a2<2;a2++)
          #pragma unroll
          for (int a3=0;a3<2;a3++){ s1[a0][a1][a2][a3]=0.f; s2[a0][a1][a2][a3]=0.f; }

    const float4* Wp = (const float4*)W;
    const float4* Up = (const float4*)u;

    for (int stage=0; stage<16; stage++){
        int ibase = itile*32 + stage*2;
        __syncthreads();
        #pragma unroll
        for (int j=0;j<2;j++){
            int idx = t + j*256;
            int il = idx>>8, r = idx&255, b = r>>2, d4 = r&3;
            float4 uv = Up[((size_t)b*I_ + ibase+il)*4 + d4];
            float* dst = sU + il*1024 + b*16 + d4;
            dst[0]  = __uint_as_float(toTf32(uv.x));
            dst[4]  = __uint_as_float(toTf32(uv.y));
            dst[8]  = __uint_as_float(toTf32(uv.z));
            dst[12] = __uint_as_float(toTf32(uv.w));
        }
        #pragma unroll
        for (int j=0;j<4;j++){
            int f = l + j*32;
            int il = f>>6, r = f&63, e = r>>2, d4 = r&3;
            float4 wv = Wp[((size_t)o*I_ + ibase+il)*64 + r];
            float* dst = sW + ((w*2+il)*16 + e)*16 + d4;
            dst[0]=wv.x; dst[4]=wv.y; dst[8]=wv.z; dst[12]=wv.w;
        }
        if (t < 128){
            int il = t>>6, b = t&63;
            sAi[il*64+b] = g_aiT[(ibase+il)*B_ + b];
        }
        __syncthreads();

        #pragma unroll
        for (int il=0; il<2; il++){
            int i = ibase + il;
            const float* uB = sU + il*1024;
            const float* wB = sW + ((size_t)(w*2+il))*256;

            uint4 bh[2], bl[2];
            #pragma unroll
            for (int et=0; et<2; et++){
                float4 wv = *(const float4*)(wB + (et*8+lg)*16 + 4*tg);
                unsigned hx=toTf32(wv.x), hy=toTf32(wv.y), hz=toTf32(wv.z), hw=toTf32(wv.w);
                bh[et] = make_uint4(hx, hy, hz, hw);
                bl[et] = make_uint4(toTf32(wv.x-__uint_as_float(hx)),
                                    toTf32(wv.y-__uint_as_float(hy)),
                                    toTf32(wv.z-__uint_as_float(hz)),
                                    toTf32(wv.w-__uint_as_float(hw)));
            }

            #pragma unroll
            for (int mt=0; mt<4; mt++){
                int r0 = mt*16 + lg;
                float4 ar0 = *(const float4*)(uB + r0*16 + 4*tg);
                float4 ar1 = *(const float4*)(uB + (r0+8)*16 + 4*tg);
                unsigned Ak0[4] = {__float_as_uint(ar0.x), __float_as_uint(ar1.x),
                                   __float_as_uint(ar0.y), __float_as_uint(ar1.y)};
                unsigned Ak1[4] = {__float_as_uint(ar0.z), __float_as_uint(ar1.z),
                                   __float_as_uint(ar0.w), __float_as_uint(ar1.w)};
                float ra0 = sAi[il*64 + r0]*0.015625f;
                float ra1 = sAi[il*64 + r0 + 8]*0.015625f;
                #pragma unroll
                for (int et=0; et<2; et++){
                    float D[4] = {0.f,0.f,0.f,0.f};
                    mma8(D, Ak0, (const unsigned*)&bh[et]);
                    mma8(D, Ak1, ((const unsigned*)&bh[et])+2);
                    mma8(D, Ak0, (const unsigned*)&bl[et]);
                    mma8(D, Ak1, ((const unsigned*)&bl[et])+2);
                    int e0 = et*8 + 2*tg;
                    float v00 = D[0]+bs[et][0], v01 = D[1]+bs[et][1];
                    float v10 = D[2]+bs[et][0], v11 = D[3]+bs[et][1];
                    __half* vp = g_Vh + (((size_t)o*I_ + i)*64 + r0)*16 + e0;
                    *(__half2*)vp         = __floats2half2_rn(v00, v01);
                    *(__half2*)(vp + 128) = __floats2half2_rn(v10, v11);
                    s1[mt][0][et][0] += ra0*v00;  s2[mt][0][et][0] += ra0*v00*v00;
                    s1[mt][0][et][1] += ra0*v01;  s2[mt][0][et][1] += ra0*v01*v01;
                    s1[mt][1][et][0] += ra1*v10;  s2[mt][1][et][0] += ra1*v10*v10;
                    s1[mt][1][et][1] += ra1*v11;  s2[mt][1][et][1] += ra1*v11*v11;
                }
            }
        }
    }

    #pragma unroll
    for (int mt=0; mt<4; mt++)
      #pragma unroll
      for (int rs=0; rs<2; rs++)
        #pragma unroll
        for (int et=0; et<2; et++)
          #pragma unroll
          for (int p=0; p<2; p++){
              int b = mt*16 + lg + rs*8;
              int e = et*8 + 2*tg + p;
              size_t gidx = (((size_t)itile*B_ + b)*O_ + o)*16 + e;
              g_p0s1[gidx] = s1[mt][rs][et][p];
              g_p0s2[gidx] = s2[mt][rs][et][p];
          }
}

// ================= K3: iter0 m-step finalize =================
__global__ __launch_bounds__(256) void k3_mstep0(const float* __restrict__ beta_a,
                                                 const float* __restrict__ beta_u){
    int t = threadIdx.x;
    int lane = t & 15;
    int unit = blockIdx.x*16 + (t>>4);
    int b = unit >> 6, o = unit & 63;
    float S1=0.f, S2=0.f;
    for (int tt=0; tt<36; tt++){
        size_t base = (((size_t)tt*B_ + b)*O_ + o)*16 + lane;
        S1 += g_p0s1[base];
        S2 += g_p0s2[base];
    }
    float rs = g_sumai[b] * 0.015625f;
    float inv = 1.f/(rs + EPSF);
    float mean = S1*inv;
    float var  = (S2 - 2.f*mean*S1 + mean*mean*rs)*inv + 1e-4f;
    float lv = logf(var), pv = var;
    #pragma unroll
    for (int k=1;k<16;k<<=1){
        lv += __shfl_xor_sync(0xffffffffu, lv, k, 16);
        pv *= __shfl_xor_sync(0xffffffffu, pv, k, 16);
    }
    float cost = rs*(16.f*beta_u[o] + lv);
    float x = 0.0005f*(beta_a[o]-cost);
    float aj = 1.f/(1.f+expf(-x));
    float p1 = sqrtf(6.283185307179586f*pv + EPSF);
    size_t mb = ((size_t)b*O_+o)*16+lane;
    g_mean[mb] = mean;
    g_i2v[mb]  = 1.f/(2.f*var + EPSF);
    if (lane==0) g_coef[b*O_+o] = aj/(p1+EPSF);
}

// ================= K4 v3: e-step + iter1 partials, V via cp.async -> smem =================
// grid (72, 64): it (16 i), b. 256 thr = 64 o x 4 eq. V tile in smem (32KB).
__global__ __launch_bounds__(256, 3) void k4_estep(){
    __shared__ float sMeanT[16*66];
    __shared__ float sI2vT[16*66];
    __shared__ float sCoef[64];
    __shared__ float sAi[16];
    __shared__ float sAP[16][64];
    __shared__ float sInv[16];
    __shared__ uint2 sV[16*256];            // [il][o*4+eq]
    int t = threadIdx.x, it = blockIdx.x, b = blockIdx.y;
    int o = t >> 2, eq = t & 3;

    // re-zero g_sumai for the next call (k3 already consumed it)
    if (it == 0 && b == 0 && t < 64) g_sumai[t] = 0.f;

    // kick off V tile loads: 16 x 8B cp.async per thread
    {
        const __half* vbase = g_Vh + (((size_t)o*I_ + it*16)*64 + b)*16 + eq*4;
        unsigned sdst = (unsigned)__cvta_generic_to_shared(&sV[t]);
        #pragma unroll
        for (int il=0; il<16; il++){
            asm volatile("cp.async.ca.shared.global [%0], [%1], 8;\n"
                :: "r"(sdst + il*2048), "l"(vbase + (size_t)il*1024));
        }
        asm volatile("cp.async.commit_group;\n");
    }

    for (int idx = t; idx < 1024; idx += 256){
        int oo = idx >> 4, e = idx & 15;
        size_t g = ((size_t)b*O_ + oo)*16 + e;
        sMeanT[e*66+oo] = g_mean[g];
        sI2vT[e*66+oo]  = g_i2v[g];
    }
    if (t < 64) sCoef[t] = g_coef[b*O_+t];
    if (t < 16) sAi[t] = g_aiT[(it*16+t)*B_ + b];
    asm volatile("cp.async.wait_group 0;\n" ::: "memory");
    __syncthreads();

    float m0 = sMeanT[(eq*4+0)*66+o], m1 = sMeanT[(eq*4+1)*66+o];
    float m2 = sMeanT[(eq*4+2)*66+o], m3 = sMeanT[(eq*4+3)*66+o];
    float w0 = sI2vT[(eq*4+0)*66+o], w1 = sI2vT[(eq*4+1)*66+o];
    float w2 = sI2vT[(eq*4+2)*66+o], w3 = sI2vT[(eq*4+3)*66+o];
    float cf = sCoef[o];

    #pragma unroll
    for (int il=0; il<16; il++){
        uint2 raw = sV[il*256 + t];
        float2 fa = __half22float2(*(__half2*)&raw.x);
        float2 fb = __half22float2(*(__half2*)&raw.y);
        float d0 = fa.x-m0, d1 = fa.y-m1, d2 = fb.x-m2, d3 = fb.y-m3;
        float ss = d0*d0*w0 + d1*d1*w1 + d2*d2*w2 + d3*d3*w3;
        ss += __shfl_xor_sync(0xffffffffu, ss, 1);
        ss += __shfl_xor_sync(0xffffffffu, ss, 2);
        if (eq == 0) sAP[il][o] = cf*__expf(-ss);
    }
    __syncthreads();

    {
        int i2 = t >> 4, j = t & 15;
        float v = sAP[i2][j] + sAP[i2][j+16] + sAP[i2][j+32] + sAP[i2][j+48];
        v += __shfl_xor_sync(0xffffffffu, v, 1, 16);
        v += __shfl_xor_sync(0xffffffffu, v, 2, 16);
        v += __shfl_xor_sync(0xffffffffu, v, 4, 16);
        v += __shfl_xor_sync(0xffffffffu, v, 8, 16);
        if (j == 0) sInv[i2] = 1.f/(v + EPSF);
    }
    __syncthreads();

    float s1[4]={0,0,0,0}, s2[4]={0,0,0,0}, accr=0.f;
    #pragma unroll
    for (int il=0; il<16; il++){
        float rra = sAP[il][o]*sInv[il]*sAi[il];
        uint2 raw = sV[il*256 + t];
        float2 fa = __half22float2(*(__half2*)&raw.x);
        float2 fb = __half22float2(*(__half2*)&raw.y);
        s1[0] += rra*fa.x; s2[0] += rra*fa.x*fa.x;
        s1[1] += rra*fa.y; s2[1] += rra*fa.y*fa.y;
        s1[2] += rra*fb.x; s2[2] += rra*fb.x*fb.x;
        s1[3] += rra*fb.y; s2[3] += rra*fb.y*fb.y;
        if (eq == 0) accr += rra;
    }
    size_t base = (((size_t)b*72 + it)*O_ + o)*16 + eq*4;
    float4 a1; a1.x=s1[0]; a1.y=s1[1]; a1.z=s1[2]; a1.w=s1[3];
    float4 a2; a2.x=s2[0]; a2.y=s2[1]; a2.z=s2[2]; a2.w=s2[3];
    *(float4*)(g_p1s1+base) = a1;
    *(float4*)(g_p1s2+base) = a2;
    if (eq == 0) g_p1rs[((size_t)b*72 + it)*O_ + o] = accr;
}

// ================= K5: iter1 finalize + output =================
__global__ __launch_bounds__(256) void k5_out(const float* __restrict__ beta_a,
                                              const float* __restrict__ beta_u,
                                              float* __restrict__ out){
    int t = threadIdx.x;
    int lane = t & 15;
    int unit = blockIdx.x*16 + (t>>4);
    int b = unit >> 6, o = unit & 63;
    float S1=0.f, S2=0.f, rs=0.f;
    for (int tt=0; tt<72; tt++){
        size_t base = (((size_t)b*72 + tt)*O_ + o)*16 + lane;
        S1 += g_p1s1[base];
        S2 += g_p1s2[base];
        rs += g_p1rs[((size_t)b*72 + tt)*O_ + o];
    }
    float inv = 1.f/(rs + EPSF);
    float mean = S1*inv;
    float var  = (S2 - 2.f*mean*S1 + mean*mean*rs)*inv + 1e-4f;
    float lv = logf(var);
    float me = mean + EPSF;
    float nn = me*me;
    #pragma unroll
    for (int k=1;k<16;k<<=1){
        lv += __shfl_xor_sync(0xffffffffu, lv, k, 16);
        nn += __shfl_xor_sync(0xffffffffu, nn, k, 16);
    }
    float cost = rs*(16.f*beta_u[o] + lv);
    float x = 0.000975f*(beta_a[o]-cost);
    float aj = 1.f/(1.f+expf(-x));
    float nrm = sqrtf(nn);
    out[((size_t)b*O_+o)*16+lane] = aj*mean/(nrm + EPSF);
}

extern "C" void kernel_launch(void* const* d_in, const int* in_sizes, int n_in,
                              void* d_out, int out_size) {
    const float* u      = (const float*)d_in[0];
    const float* W      = (const float*)d_in[1];
    const float* beta_a = (const float*)d_in[2];
    const float* beta_u = (const float*)d_in[3];
    const float* bias   = (const float*)d_in[4];
    float* out = (float*)d_out;

    k1_ai<<<(B_*I_+255)/256, 256>>>(u);          // launch 1
    k2_votes<<<dim3(36, 8), 256>>>(u, W, bias);  // launch 2
    k3_mstep0<<<256, 256>>>(beta_a, beta_u);     // launch 3
    k4_estep<<<dim3(72, 64), 256>>>();           // launch 4 -> ncu slot
    k5_out<<<256, 256>>>(beta_a, beta_u, out);   // launch 5
}

// round 17
// speedup vs baseline: 1.2116x; 1.1389x over previous
#include <cuda_runtime.h>
#include <cuda_fp16.h>
#include <cstdint>
#include <math.h>

#define B_ 64
#define O_ 64
#define I_ 1152
#define EPSF 1e-8f

// ---- scratch ----
__device__ __half g_Vh[75497472];        // [o][i][b][e] fp16
__device__ float g_aiT[I_*B_];
__device__ float g_sumai[B_];            // zero-init; re-zeroed in k4 each call
__device__ float g_p0s1[36*B_*O_*16];
__device__ float g_p0s2[36*B_*O_*16];
__device__ float g_mean[B_*O_*16];
__device__ float g_i2v[B_*O_*16];
__device__ float g_coef[B_*O_];
__device__ float g_p1s1[B_*72*O_*16];
__device__ float g_p1s2[B_*72*O_*16];
__device__ float g_p1rs[B_*72*O_];

__device__ __forceinline__ unsigned toTf32(float f){
    unsigned r; asm("cvt.rna.tf32.f32 %0,%1;" : "=r"(r) : "f"(f)); return r;
}
__device__ __forceinline__ void mma8(float* d, const unsigned* a, const unsigned* b){
    asm volatile("mma.sync.aligned.m16n8k8.row.col.f32.tf32.tf32.f32 "
        "{%0,%1,%2,%3},{%4,%5,%6,%7},{%8,%9},{%0,%1,%2,%3};"
        : "+f"(d[0]),"+f"(d[1]),"+f"(d[2]),"+f"(d[3])
        : "r"(a[0]),"r"(a[1]),"r"(a[2]),"r"(a[3]),"r"(b[0]),"r"(b[1]));
}
__device__ __forceinline__ void cpa16(void* dst, const void* src){
    unsigned d = (unsigned)__cvta_generic_to_shared(dst);
    asm volatile("cp.async.ca.shared.global [%0], [%1], 16;\n" :: "r"(d), "l"(src));
}

// ================= dummy (ncu slot alignment) =================
__global__ void knop(){}

// ================= K1: a_i (+ atomic per-b sum) =================
__global__ __launch_bounds__(256) void k1_ai(const float* __restrict__ u){
    int idx = blockIdx.x*256 + threadIdx.x;
    if (idx >= B_*I_) return;
    const float4* up = ((const float4*)u) + (size_t)idx*4;
    float s = 0.f;
    #pragma unroll
    for (int k=0;k<4;k++){
        float4 v = up[k];
        float x0=v.x+EPSF, x1=v.y+EPSF, x2=v.z+EPSF, x3=v.w+EPSF;
        s += x0*x0+x1*x1+x2*x2+x3*x3;
    }
    float a = sqrtf(s);
    int b = idx / I_, i = idx % I_;
    g_aiT[i*B_+b] = a;
    atomicAdd(&g_sumai[b], a);
}

// ================= K2 v8: cp.async triple-buffered tf32 mma votes =================
// grid (36, 8): itile (32 i), otile (8 o). Warp w -> o = otile*8 + w.
// 16 stages x 2 i. Buffers: u [il][b][d] pitch20 (2560 fl) | W [w][il][e][d] pitch20
// (5120 fl) | ai (128 fl). BUF = 7808 floats; 3 bufs dynamic smem (93696 B).
#define K2_BUF 7808
__global__ __launch_bounds__(256) void k2_votes(const float* __restrict__ u,
                                               const float* __restrict__ W,
                                               const float* __restrict__ bias){
    extern __shared__ float DSM[];
    int t = threadIdx.x;
    int w = t>>5, l = t&31, lg = l>>2, tg = l&3;
    int itile = blockIdx.x;
    int o = blockIdx.y*8 + w;
    int itbase = itile*32;

    float bs[2][2];
    #pragma unroll
    for (int et=0;et<2;et++)
      #pragma unroll
      for (int p=0;p<2;p++) bs[et][p] = bias[o*16 + et*8 + 2*tg + p] + EPSF;

    float s1[4][2][2][2], s2[4][2][2][2];   // [mt][rowsel][et][p]
    #pragma unroll
    for (int a0=0;a0<4;a0++)
      #pragma unroll
      for (int a1=0;a1<2;a1++)
        #pragma unroll
        for (int a2=0;a2<2;a2++)
          #pragma unroll
          for (int a3=0;a3<2;a3++){ s1[a0][a1][a2][a3]=0.f; s2[a0][a1][a2][a3]=0.f; }

    // staging index decompositions (fixed per thread)
    int u_il[2], u_b[2], u_d4[2];
    #pragma unroll
    for (int j=0;j<2;j++){
        int idx = t + j*256;
        u_il[j] = idx>>8; int r = idx&255; u_b[j] = r>>2; u_d4[j] = r&3;
    }
    int w_il[4], w_e[4], w_d4[4];
    #pragma unroll
    for (int j=0;j<4;j++){
        int f = l + j*32;
        w_il[j] = f>>6; int r = f&63; w_e[j] = r>>2; w_d4[j] = r&3;
    }
    int a_il = (t>>4)&1, a_b4 = t&15;   // used when t<32

    auto prefetch = [&](int s){
        float* buf = DSM + (s%3)*K2_BUF;
        int ib = itbase + s*2;
        #pragma unroll
        for (int j=0;j<2;j++){
            cpa16(buf + u_il[j]*1280 + u_b[j]*20 + u_d4[j]*4,
                  u + ((size_t)u_b[j]*I_ + ib + u_il[j])*16 + u_d4[j]*4);
        }
        #pragma unroll
        for (int j=0;j<4;j++){
            cpa16(buf + 2560 + w*640 + w_il[j]*320 + w_e[j]*20 + w_d4[j]*4,
                  W + ((size_t)o*I_ + ib + w_il[j])*256 + w_e[j]*16 + w_d4[j]*4);
        }
        if (t < 32){
            cpa16(buf + 7680 + a_il*64 + a_b4*4,
                  g_aiT + (ib + a_il)*64 + a_b4*4);
        }
        asm volatile("cp.async.commit_group;\n");
    };

    prefetch(0);
    prefetch(1);

    for (int s=0; s<16; s++){
        if (s < 15) asm volatile("cp.async.wait_group 1;\n" ::: "memory");
        else        asm volatile("cp.async.wait_group 0;\n" ::: "memory");
        __syncthreads();                 // buf s visible; compute(s-1) done by all
        if (s+2 < 16) prefetch(s+2);     // writes buf (s+2)%3 == (s-1)%3, now safe

        float* buf = DSM + (s%3)*K2_BUF;
        int ibase = itbase + s*2;

        #pragma unroll
        for (int il=0; il<2; il++){
            int i = ibase + il;
            const float* uB = buf + il*1280;
            const float* wB = buf + 2560 + w*640 + il*320;
            const float* aB = buf + 7680 + il*64;

            uint4 bh[2], bl[2];
            #pragma unroll
            for (int et=0; et<2; et++){
                const float* p = wB + (et*8+lg)*20 + tg;
                float w0=p[0], w1=p[4], w2=p[8], w3=p[12];
                unsigned hx=toTf32(w0), hy=toTf32(w1), hz=toTf32(w2), hw=toTf32(w3);
                bh[et] = make_uint4(hx, hy, hz, hw);
                bl[et] = make_uint4(toTf32(w0-__uint_as_float(hx)),
                                    toTf32(w1-__uint_as_float(hy)),
                                    toTf32(w2-__uint_as_float(hz)),
                                    toTf32(w3-__uint_as_float(hw)));
            }

            #pragma unroll
            for (int mt=0; mt<4; mt++){
                int r0 = mt*16 + lg;
                const float* pa = uB + r0*20 + tg;
                const float* pb = uB + (r0+8)*20 + tg;
                unsigned Ak0[4] = {toTf32(pa[0]), toTf32(pb[0]), toTf32(pa[4]), toTf32(pb[4])};
                unsigned Ak1[4] = {toTf32(pa[8]), toTf32(pb[8]), toTf32(pa[12]), toTf32(pb[12])};
                float ra0 = aB[r0]*0.015625f;
                float ra1 = aB[r0+8]*0.015625f;
                #pragma unroll
                for (int et=0; et<2; et++){
                    float D[4] = {0.f,0.f,0.f,0.f};
                    mma8(D, Ak0, (const unsigned*)&bh[et]);
                    mma8(D, Ak1, ((const unsigned*)&bh[et])+2);
                    mma8(D, Ak0, (const unsigned*)&bl[et]);
                    mma8(D, Ak1, ((const unsigned*)&bl[et])+2);
                    int e0 = et*8 + 2*tg;
                    float v00 = D[0]+bs[et][0], v01 = D[1]+bs[et][1];
                    float v10 = D[2]+bs[et][0], v11 = D[3]+bs[et][1];
                    __half* vp = g_Vh + (((size_t)o*I_ + i)*64 + r0)*16 + e0;
                    *(__half2*)vp         = __floats2half2_rn(v00, v01);
                    *(__half2*)(vp + 128) = __floats2half2_rn(v10, v11);
                    s1[mt][0][et][0] += ra0*v00;  s2[mt][0][et][0] += ra0*v00*v00;
                    s1[mt][0][et][1] += ra0*v01;  s2[mt][0][et][1] += ra0*v01*v01;
                    s1[mt][1][et][0] += ra1*v10;  s2[mt][1][et][0] += ra1*v10*v10;
                    s1[mt][1][et][1] += ra1*v11;  s2[mt][1][et][1] += ra1*v11*v11;
                }
            }
        }
    }

    // write iter0 partials [itile][b][o][e]; each o owned by one warp
    #pragma unroll
    for (int mt=0; mt<4; mt++)
      #pragma unroll
      for (int rs=0; rs<2; rs++)
        #pragma unroll
        for (int et=0; et<2; et++)
          #pragma unroll
          for (int p=0; p<2; p++){
              int b = mt*16 + lg + rs*8;
              int e = et*8 + 2*tg + p;
              size_t gidx = (((size_t)itile*B_ + b)*O_ + o)*16 + e;
              g_p0s1[gidx] = s1[mt][rs][et][p];
              g_p0s2[gidx] = s2[mt][rs][et][p];
          }
}

// ================= K3: iter0 m-step finalize =================
__global__ __launch_bounds__(256) void k3_mstep0(const float* __restrict__ beta_a,
                                                 const float* __restrict__ beta_u){
    int t = threadIdx.x;
    int lane = t & 15;
    int unit = blockIdx.x*16 + (t>>4);
    int b = unit >> 6, o = unit & 63;
    float S1=0.f, S2=0.f;
    for (int tt=0; tt<36; tt++){
        size_t base = (((size_t)tt*B_ + b)*O_ + o)*16 + lane;
        S1 += g_p0s1[base];
        S2 += g_p0s2[base];
    }
    float rs = g_sumai[b] * 0.015625f;
    float inv = 1.f/(rs + EPSF);
    float mean = S1*inv;
    float var  = (S2 - 2.f*mean*S1 + mean*mean*rs)*inv + 1e-4f;
    float lv = logf(var), pv = var;
    #pragma unroll
    for (int k=1;k<16;k<<=1){
        lv += __shfl_xor_sync(0xffffffffu, lv, k, 16);
        pv *= __shfl_xor_sync(0xffffffffu, pv, k, 16);
    }
    float cost = rs*(16.f*beta_u[o] + lv);
    float x = 0.0005f*(beta_a[o]-cost);
    float aj = 1.f/(1.f+expf(-x));
    float p1 = sqrtf(6.283185307179586f*pv + EPSF);
    size_t mb = ((size_t)b*O_+o)*16+lane;
    g_mean[mb] = mean;
    g_i2v[mb]  = 1.f/(2.f*var + EPSF);
    if (lane==0) g_coef[b*O_+o] = aj/(p1+EPSF);
}

// ================= K4 v4: e-step + iter1 partials, cp.async V + reg-resident phase3 =================
// grid (72, 64): it (16 i), b. 256 thr = 64 o x 4 eq.
__global__ __launch_bounds__(256, 3) void k4_estep(){
    __shared__ float sMeanT[16*66];
    __shared__ float sI2vT[16*66];
    __shared__ float sCoef[64];
    __shared__ float sAi[16];
    __shared__ float sAP[16][64];
    __shared__ float sInv[16];
    __shared__ uint2 sV[16*256];            // [il][o*4+eq]
    int t = threadIdx.x, it = blockIdx.x, b = blockIdx.y;
    int o = t >> 2, eq = t & 3;

    // re-zero g_sumai for the next call (k3 already consumed it)
    if (it == 0 && b == 0 && t < 64) g_sumai[t] = 0.f;

    // kick off V tile loads: 16 x 8B cp.async per thread
    {
        const __half* vbase = g_Vh + (((size_t)o*I_ + it*16)*64 + b)*16 + eq*4;
        unsigned sdst = (unsigned)__cvta_generic_to_shared(&sV[t]);
        #pragma unroll
        for (int il=0; il<16; il++){
            asm volatile("cp.async.ca.shared.global [%0], [%1], 8;\n"
                :: "r"(sdst + il*2048), "l"(vbase + (size_t)il*1024));
        }
        asm volatile("cp.async.commit_group;\n");
    }

    for (int idx = t; idx < 1024; idx += 256){
        int oo = idx >> 4, e = idx & 15;
        size_t g = ((size_t)b*O_ + oo)*16 + e;
        sMeanT[e*66+oo] = g_mean[g];
        sI2vT[e*66+oo]  = g_i2v[g];
    }
    if (t < 64) sCoef[t] = g_coef[b*O_+t];
    if (t < 16) sAi[t] = g_aiT[(it*16+t)*B_ + b];
    asm volatile("cp.async.wait_group 0;\n" ::: "memory");
    __syncthreads();

    float m0 = sMeanT[(eq*4+0)*66+o], m1 = sMeanT[(eq*4+1)*66+o];
    float m2 = sMeanT[(eq*4+2)*66+o], m3 = sMeanT[(eq*4+3)*66+o];
    float w0 = sI2vT[(eq*4+0)*66+o], w1 = sI2vT[(eq*4+1)*66+o];
    float w2 = sI2vT[(eq*4+2)*66+o], w3 = sI2vT[(eq*4+3)*66+o];
    float cf = sCoef[o];

    uint2 vr[16];
    #pragma unroll
    for (int il=0; il<16; il++){
        uint2 raw = sV[il*256 + t];
        vr[il] = raw;
        float2 fa = __half22float2(*(__half2*)&raw.x);
        float2 fb = __half22float2(*(__half2*)&raw.y);
        float d0 = fa.x-m0, d1 = fa.y-m1, d2 = fb.x-m2, d3 = fb.y-m3;
        float ss = d0*d0*w0 + d1*d1*w1 + d2*d2*w2 + d3*d3*w3;
        ss += __shfl_xor_sync(0xffffffffu, ss, 1);
        ss += __shfl_xor_sync(0xffffffffu, ss, 2);
        if (eq == 0) sAP[il][o] = cf*__expf(-ss);
    }
    __syncthreads();

    {
        int i2 = t >> 4, j = t & 15;
        float v = sAP[i2][j] + sAP[i2][j+16] + sAP[i2][j+32] + sAP[i2][j+48];
        v += __shfl_xor_sync(0xffffffffu, v, 1, 16);
        v += __shfl_xor_sync(0xffffffffu, v, 2, 16);
        v += __shfl_xor_sync(0xffffffffu, v, 4, 16);
        v += __shfl_xor_sync(0xffffffffu, v, 8, 16);
        if (j == 0) sInv[i2] = 1.f/(v + EPSF);
    }
    __syncthreads();

    float s1[4]={0,0,0,0}, s2[4]={0,0,0,0}, accr=0.f;
    #pragma unroll
    for (int il=0; il<16; il++){
        float rra = sAP[il][o]*sInv[il]*sAi[il];
        float2 fa = __half22float2(*(__half2*)&vr[il].x);
        float2 fb = __half22float2(*(__half2*)&vr[il].y);
        s1[0] += rra*fa.x; s2[0] += rra*fa.x*fa.x;
        s1[1] += rra*fa.y; s2[1] += rra*fa.y*fa.y;
        s1[2] += rra*fb.x; s2[2] += rra*fb.x*fb.x;
        s1[3] += rra*fb.y; s2[3] += rra*fb.y*fb.y;
        if (eq == 0) accr += rra;
    }
    size_t base = (((size_t)b*72 + it)*O_ + o)*16 + eq*4;
    float4 a1; a1.x=s1[0]; a1.y=s1[1]; a1.z=s1[2]; a1.w=s1[3];
    float4 a2; a2.x=s2[0]; a2.y=s2[1]; a2.z=s2[2]; a2.w=s2[3];
    *(float4*)(g_p1s1+base) = a1;
    *(float4*)(g_p1s2+base) = a2;
    if (eq == 0) g_p1rs[((size_t)b*72 + it)*O_ + o] = accr;
}

// ================= K5: iter1 finalize + output =================
__global__ __launch_bounds__(256) void k5_out(const float* __restrict__ beta_a,
                                              const float* __restrict__ beta_u,
                                              float* __restrict__ out){
    int t = threadIdx.x;
    int lane = t & 15;
    int unit = blockIdx.x*16 + (t>>4);
    int b = unit >> 6, o = unit & 63;
    float S1=0.f, S2=0.f, rs=0.f;
    for (int tt=0; tt<72; tt++){
        size_t base = (((size_t)b*72 + tt)*O_ + o)*16 + lane;
        S1 += g_p1s1[base];
        S2 += g_p1s2[base];
        rs += g_p1rs[((size_t)b*72 + tt)*O_ + o];
    }
    float inv = 1.f/(rs + EPSF);
    float mean = S1*inv;
    float var  = (S2 - 2.f*mean*S1 + mean*mean*rs)*inv + 1e-4f;
    float lv = logf(var);
    float me = mean + EPSF;
    float nn = me*me;
    #pragma unroll
    for (int k=1;k<16;k<<=1){
        lv += __shfl_xor_sync(0xffffffffu, lv, k, 16);
        nn += __shfl_xor_sync(0xffffffffu, nn, k, 16);
    }
    float cost = rs*(16.f*beta_u[o] + lv);
    float x = 0.000975f*(beta_a[o]-cost);
    float aj = 1.f/(1.f+expf(-x));
    float nrm = sqrtf(nn);
    out[((size_t)b*O_+o)*16+lane] = aj*mean/(nrm + EPSF);
}

extern "C" void kernel_launch(void* const* d_in, const int* in_sizes, int n_in,
                              void* d_out, int out_size) {
    const float* u      = (const float*)d_in[0];
    const float* W      = (const float*)d_in[1];
    const float* beta_a = (const float*)d_in[2];
    const float* beta_u = (const float*)d_in[3];
    const float* bias   = (const float*)d_in[4];
    float* out = (float*)d_out;

    static bool attr_set = false;
    if (!attr_set){
        cudaFuncSetAttribute(k2_votes, cudaFuncAttributeMaxDynamicSharedMemorySize,
                             3*K2_BUF*4);
        attr_set = true;
    }

    k1_ai<<<(B_*I_+255)/256, 256>>>(u);                       // launch 1
    knop<<<1, 32>>>();                                         // launch 2
    knop<<<1, 32>>>();                                         // launch 3
    k2_votes<<<dim3(36, 8), 256, 3*K2_BUF*4>>>(u, W, bias);   // launch 4 -> ncu slot
    k3_mstep0<<<256, 256>>>(beta_a, beta_u);                   // launch 5
    k4_estep<<<dim3(72, 64), 256>>>();                         // launch 6
    k5_out<<<256, 256>>>(beta_a, beta_u, out);                 // launch 7
}